// round 4
// baseline (speedup 1.0000x reference)
#include <cuda_runtime.h>
#include <cstdint>

// SGConv K=2: h = P (P x), P = D^-1/2 (A + I) D^-1/2, deg over dst (+ self loop).
// Algebraic form: with z = dis .* h,  out[d] = dis[d]*(z[d] + sum_{s in N(d)} z[s]).
// So per-edge coefficients vanish: CSR stores ONLY the src index (4B/edge).
// Pipeline: degree -> scan (rowptr + cursor seed + dis) -> scatter(col) ->
//           z0 = dis.*x -> hop1 (z-space out: *dis^2) -> hop2 (h-space out: *dis).
// Hops: one warp per node, 3 accumulators/lane, 4-edge unroll; features (19.2MB)
// are L2-resident -> hops run at the L2 bandwidth roofline, no atomics.

#define N_NODES 50000
#define N_EDGES 800000
#define N_FEAT  96
#define SCAN_B  1024
#define N_CHUNK ((N_NODES + SCAN_B - 1) / SCAN_B)   // 49

// ---------------- device scratch (allocation-free rule: __device__ globals) ----
__device__ int   g_is64;                    // 1 if edge_index is int64, 0 if int32
__device__ int   g_counts[N_NODES];         // in-degree (dst)
__device__ int   g_cursor[N_NODES];         // scatter cursors (seeded = excl prefix)
__device__ int   g_rowptr[N_NODES + 1];     // CSR row pointers (by dst)
__device__ int   g_bsum[N_CHUNK];           // per-chunk sums
__device__ float g_dis[N_NODES];            // (deg+1)^-1/2
__device__ int   g_col[N_EDGES];            // src per CSR slot
__device__ float g_z0[(size_t)N_NODES * N_FEAT];  // dis .* x
__device__ float g_z1[(size_t)N_NODES * N_FEAT];  // hop-1 output (z-space)

// ---------------- dtype detection ---------------------------------------------
// Values in [0, 50000). int64 little-endian => every odd 32-bit word is 0.
// int32 => odd words ~uniform in [0,50000): P(all 2048 samples zero) ~ 0.
__global__ void detect_kernel(const void* ei) {
    __shared__ int nz;
    if (threadIdx.x == 0) nz = 0;
    __syncthreads();
    const int* w = (const int*)ei;
    int local = 0;
    for (int i = threadIdx.x; i < 2048; i += blockDim.x)
        if (w[2 * i + 1] != 0) local = 1;
    if (local) atomicExch(&nz, 1);
    __syncthreads();
    if (threadIdx.x == 0) g_is64 = (nz == 0) ? 1 : 0;
}

__device__ __forceinline__ int edge_src(const void* ei, int e) {
    if (g_is64) return (int)((const long long*)ei)[e];
    return ((const int*)ei)[e];
}
__device__ __forceinline__ int edge_dst(const void* ei, int e) {
    if (g_is64) return (int)((const long long*)ei)[N_EDGES + e];
    return ((const int*)ei)[N_EDGES + e];
}

// ---------------- degree --------------------------------------------------------
__global__ void degree_kernel(const void* __restrict__ ei) {
    int e = blockIdx.x * blockDim.x + threadIdx.x;
    if (e < N_EDGES) atomicAdd(&g_counts[edge_dst(ei, e)], 1);
}

// ---------------- scan pass 1: coalesced chunk sums + dis -----------------------
__global__ void __launch_bounds__(SCAN_B) reduce_dis_kernel() {
    const int tid = threadIdx.x, lane = tid & 31, wid = tid >> 5;
    const int i = blockIdx.x * SCAN_B + tid;
    int c = 0;
    if (i < N_NODES) {
        c = g_counts[i];
        g_dis[i] = rsqrtf((float)(c + 1));   // +1 self loop
    }
    __shared__ int wsum[32];
    int v = c;
    #pragma unroll
    for (int off = 16; off > 0; off >>= 1) v += __shfl_down_sync(0xFFFFFFFFu, v, off);
    if (lane == 0) wsum[wid] = v;
    __syncthreads();
    if (wid == 0) {
        int s = wsum[lane];
        #pragma unroll
        for (int off = 16; off > 0; off >>= 1) s += __shfl_down_sync(0xFFFFFFFFu, s, off);
        if (lane == 0) g_bsum[blockIdx.x] = s;
    }
}

// ---------------- scan pass 2: per-chunk coalesced block scan -------------------
__global__ void __launch_bounds__(SCAN_B) scan_write_kernel() {
    const int tid = threadIdx.x, lane = tid & 31, wid = tid >> 5;
    const int i = blockIdx.x * SCAN_B + tid;

    // chunk offset = sum of bsum[0 .. blockIdx-1] (64-thread reduce)
    __shared__ int s_off[2];
    if (tid < 64) {
        int v = (tid < blockIdx.x && tid < N_CHUNK) ? g_bsum[tid] : 0;
        #pragma unroll
        for (int off = 16; off > 0; off >>= 1) v += __shfl_down_sync(0xFFFFFFFFu, v, off);
        if ((tid & 31) == 0) s_off[tid >> 5] = v;
    }

    int c = (i < N_NODES) ? g_counts[i] : 0;

    __shared__ int wsum[32];
    int incl = c;
    #pragma unroll
    for (int off = 1; off < 32; off <<= 1) {
        int t = __shfl_up_sync(0xFFFFFFFFu, incl, off);
        if (lane >= off) incl += t;
    }
    if (lane == 31) wsum[wid] = incl;
    __syncthreads();
    if (wid == 0) {
        int v = wsum[lane];
        #pragma unroll
        for (int off = 1; off < 32; off <<= 1) {
            int t = __shfl_up_sync(0xFFFFFFFFu, v, off);
            if (lane >= off) v += t;
        }
        wsum[lane] = v;
    }
    __syncthreads();

    int offset = s_off[0] + s_off[1] + (wid > 0 ? wsum[wid - 1] : 0);
    if (i < N_NODES) {
        int inc_total = offset + incl;
        g_rowptr[i + 1] = inc_total;
        g_cursor[i]     = inc_total - c;   // exclusive prefix = row start
    }
    if (blockIdx.x == 0 && tid == 0) g_rowptr[0] = 0;
}

// ---------------- scatter: cursor atomic + one 4B store per edge ---------------
__global__ void scatter_kernel(const void* __restrict__ ei) {
    int e = blockIdx.x * blockDim.x + threadIdx.x;
    if (e >= N_EDGES) return;
    int s = edge_src(ei, e);
    int d = edge_dst(ei, e);
    int pos = atomicAdd(&g_cursor[d], 1);
    g_col[pos] = s;
}

// ---------------- z0 = dis .* x (streaming, float4) -----------------------------
__global__ void __launch_bounds__(256) scale_kernel(const float* __restrict__ x) {
    const size_t TOT4 = (size_t)N_NODES * N_FEAT / 4;   // 1.2M float4
    size_t i = (size_t)blockIdx.x * blockDim.x + threadIdx.x;
    if (i >= TOT4) return;
    int node = (int)(i / (N_FEAT / 4));
    float s = g_dis[node];
    float4 v = ((const float4*)x)[i];
    v.x *= s; v.y *= s; v.z *= s; v.w *= s;
    ((float4*)g_z0)[i] = v;
}

// ---------------- hop: one warp per node, 3 accumulators, 4-edge unroll ---------
// out[d] = scale(d) * (zin[d] + sum zin[src]); SQ selects dis^2 (z-space) vs dis.
template <bool SQ>
__global__ void __launch_bounds__(256) hop_kernel(const float* __restrict__ zin,
                                                  float* __restrict__ out) {
    const int node = blockIdx.x * (blockDim.x >> 5) + (threadIdx.x >> 5);
    if (node >= N_NODES) return;
    const int lane = threadIdx.x & 31;

    const float* hn = zin + (size_t)node * N_FEAT;
    float a0 = hn[lane];
    float a1 = hn[lane + 32];
    float a2 = hn[lane + 64];

    int e = g_rowptr[node];
    const int end = g_rowptr[node + 1];

    for (; e + 3 < end; e += 4) {
        int s0 = g_col[e];
        int s1 = g_col[e + 1];
        int s2 = g_col[e + 2];
        int s3 = g_col[e + 3];
        const float* h0 = zin + (size_t)s0 * N_FEAT;
        const float* h1 = zin + (size_t)s1 * N_FEAT;
        const float* h2 = zin + (size_t)s2 * N_FEAT;
        const float* h3 = zin + (size_t)s3 * N_FEAT;
        float x00 = h0[lane], x01 = h0[lane + 32], x02 = h0[lane + 64];
        float x10 = h1[lane], x11 = h1[lane + 32], x12 = h1[lane + 64];
        float x20 = h2[lane], x21 = h2[lane + 32], x22 = h2[lane + 64];
        float x30 = h3[lane], x31 = h3[lane + 32], x32 = h3[lane + 64];
        a0 += x00; a1 += x01; a2 += x02;
        a0 += x10; a1 += x11; a2 += x12;
        a0 += x20; a1 += x21; a2 += x22;
        a0 += x30; a1 += x31; a2 += x32;
    }
    for (; e < end; e++) {
        int s = g_col[e];
        const float* hs = zin + (size_t)s * N_FEAT;
        a0 += hs[lane]; a1 += hs[lane + 32]; a2 += hs[lane + 64];
    }

    float sc = g_dis[node];
    if (SQ) sc = sc * sc;
    float* ho = out + (size_t)node * N_FEAT;
    ho[lane]      = sc * a0;
    ho[lane + 32] = sc * a1;
    ho[lane + 64] = sc * a2;
}

// ---------------- launch --------------------------------------------------------
extern "C" void kernel_launch(void* const* d_in, const int* in_sizes, int n_in,
                              void* d_out, int out_size) {
    const float* x  = (const float*)d_in[0];
    const void*  ei = d_in[1];
    float* out = (float*)d_out;

    int* cnt = nullptr; float* z0 = nullptr; float* z1 = nullptr;
    cudaGetSymbolAddress((void**)&cnt, g_counts);
    cudaGetSymbolAddress((void**)&z0, g_z0);
    cudaGetSymbolAddress((void**)&z1, g_z1);

    const int TB = 256;
    cudaMemsetAsync(cnt, 0, N_NODES * sizeof(int));
    detect_kernel<<<1, 256>>>(ei);
    degree_kernel<<<(N_EDGES + TB - 1) / TB, TB>>>(ei);
    reduce_dis_kernel<<<N_CHUNK, SCAN_B>>>();
    scan_write_kernel<<<N_CHUNK, SCAN_B>>>();
    scatter_kernel<<<(N_EDGES + TB - 1) / TB, TB>>>(ei);

    const size_t TOT4 = (size_t)N_NODES * N_FEAT / 4;
    scale_kernel<<<(int)((TOT4 + TB - 1) / TB), TB>>>(x);

    const int warps_per_block = TB / 32;
    const int hop_grid = (N_NODES + warps_per_block - 1) / warps_per_block;
    hop_kernel<true ><<<hop_grid, TB>>>(z0, z1);   // z-space intermediate
    hop_kernel<false><<<hop_grid, TB>>>(z1, out);  // final h-space
}

// round 5
// speedup vs baseline: 1.0500x; 1.0500x over previous
#include <cuda_runtime.h>
#include <cuda_fp16.h>
#include <cstdint>

// SGConv K=2: h = P (P x), P = D^-1/2 (A + I) D^-1/2, deg over dst (+ self loop).
// Algebraic form: with z = dis .* h, out[d] = dis[d]*(z[d] + sum_{s in N(d)} z[s]).
// z0/z1 intermediates stored in FP16 (fp32 accumulate) -> hop gather traffic
// halves (384B -> 192B per edge). CSR build is atomic-light: degree pass records
// each edge's within-row rank, so scatter is atomic-free.
// Hops: one warp per node, 4 fp32 accumulators/lane, 4-edge unroll; L2-resident.

#define N_NODES 50000
#define N_EDGES 800000
#define N_FEAT  96
#define ROW_U   (N_FEAT / 2)                 // 48 u32 (half2) per row
#define SCAN_B  1024
#define N_CHUNK ((N_NODES + SCAN_B - 1) / SCAN_B)   // 49

// ---------------- device scratch (allocation-free rule: __device__ globals) ----
__device__ int   g_is64;
__device__ int   g_counts[N_NODES];          // in-degree (dst)
__device__ int   g_rowptr[N_NODES + 1];      // CSR row pointers (by dst)
__device__ int   g_bsum[N_CHUNK];
__device__ float g_dis[N_NODES];             // (deg+1)^-1/2
__device__ int   g_pos[N_EDGES];             // within-row rank of edge e
__device__ int   g_col[N_EDGES];             // src per CSR slot
// +32 u32 pad: hop loads row[32+lane] unconditionally (lanes>=16 read junk that
// is never stored); pad keeps the last row's over-read in bounds.
__device__ unsigned int g_z0h[(size_t)N_NODES * ROW_U + 32];
__device__ unsigned int g_z1h[(size_t)N_NODES * ROW_U + 32];

// ---------------- dtype detection ---------------------------------------------
__global__ void detect_kernel(const void* ei) {
    __shared__ int nz;
    if (threadIdx.x == 0) nz = 0;
    __syncthreads();
    const int* w = (const int*)ei;
    int local = 0;
    for (int i = threadIdx.x; i < 2048; i += blockDim.x)
        if (w[2 * i + 1] != 0) local = 1;
    if (local) atomicExch(&nz, 1);
    __syncthreads();
    if (threadIdx.x == 0) g_is64 = (nz == 0) ? 1 : 0;
}

__device__ __forceinline__ int edge_src(const void* ei, int e) {
    if (g_is64) return (int)((const long long*)ei)[e];
    return ((const int*)ei)[e];
}
__device__ __forceinline__ int edge_dst(const void* ei, int e) {
    if (g_is64) return (int)((const long long*)ei)[N_EDGES + e];
    return ((const int*)ei)[N_EDGES + e];
}

// ---------------- degree + edge rank -------------------------------------------
__global__ void degree_kernel(const void* __restrict__ ei) {
    int e = blockIdx.x * blockDim.x + threadIdx.x;
    if (e < N_EDGES) g_pos[e] = atomicAdd(&g_counts[edge_dst(ei, e)], 1);
}

// ---------------- scan pass 1: coalesced chunk sums + dis -----------------------
__global__ void __launch_bounds__(SCAN_B) reduce_dis_kernel() {
    const int tid = threadIdx.x, lane = tid & 31, wid = tid >> 5;
    const int i = blockIdx.x * SCAN_B + tid;
    int c = 0;
    if (i < N_NODES) {
        c = g_counts[i];
        g_dis[i] = rsqrtf((float)(c + 1));   // +1 self loop
    }
    __shared__ int wsum[32];
    int v = c;
    #pragma unroll
    for (int off = 16; off > 0; off >>= 1) v += __shfl_down_sync(0xFFFFFFFFu, v, off);
    if (lane == 0) wsum[wid] = v;
    __syncthreads();
    if (wid == 0) {
        int s = wsum[lane];
        #pragma unroll
        for (int off = 16; off > 0; off >>= 1) s += __shfl_down_sync(0xFFFFFFFFu, s, off);
        if (lane == 0) g_bsum[blockIdx.x] = s;
    }
}

// ---------------- scan pass 2: per-chunk coalesced block scan -------------------
__global__ void __launch_bounds__(SCAN_B) scan_write_kernel() {
    const int tid = threadIdx.x, lane = tid & 31, wid = tid >> 5;
    const int i = blockIdx.x * SCAN_B + tid;

    __shared__ int s_off[2];
    if (tid < 64) {
        int v = (tid < blockIdx.x && tid < N_CHUNK) ? g_bsum[tid] : 0;
        #pragma unroll
        for (int off = 16; off > 0; off >>= 1) v += __shfl_down_sync(0xFFFFFFFFu, v, off);
        if ((tid & 31) == 0) s_off[tid >> 5] = v;
    }

    int c = (i < N_NODES) ? g_counts[i] : 0;

    __shared__ int wsum[32];
    int incl = c;
    #pragma unroll
    for (int off = 1; off < 32; off <<= 1) {
        int t = __shfl_up_sync(0xFFFFFFFFu, incl, off);
        if (lane >= off) incl += t;
    }
    if (lane == 31) wsum[wid] = incl;
    __syncthreads();
    if (wid == 0) {
        int v = wsum[lane];
        #pragma unroll
        for (int off = 1; off < 32; off <<= 1) {
            int t = __shfl_up_sync(0xFFFFFFFFu, v, off);
            if (lane >= off) v += t;
        }
        wsum[lane] = v;
    }
    __syncthreads();

    int offset = s_off[0] + s_off[1] + (wid > 0 ? wsum[wid - 1] : 0);
    if (i < N_NODES) g_rowptr[i + 1] = offset + incl;
    if (blockIdx.x == 0 && tid == 0) g_rowptr[0] = 0;
}

// ---------------- scatter: atomic-free (rowptr[d] + rank) -----------------------
__global__ void scatter_kernel(const void* __restrict__ ei) {
    int e = blockIdx.x * blockDim.x + threadIdx.x;
    if (e >= N_EDGES) return;
    int s = edge_src(ei, e);
    int d = edge_dst(ei, e);
    g_col[g_rowptr[d] + g_pos[e]] = s;
}

// ---------------- z0 = half(dis .* x) -------------------------------------------
__global__ void __launch_bounds__(256) scale_kernel(const float* __restrict__ x) {
    const size_t TOT = (size_t)N_NODES * ROW_U;   // one half2 per thread
    size_t i = (size_t)blockIdx.x * blockDim.x + threadIdx.x;
    if (i >= TOT) return;
    int node = (int)(i / ROW_U);
    float s = g_dis[node];
    float2 v = ((const float2*)x)[i];
    __half2 h = __floats2half2_rn(s * v.x, s * v.y);
    g_z0h[i] = *(unsigned int*)&h;
}

// ---------------- hop: one warp per node, fp16 gather, fp32 accumulate ----------
// Lane owns features {2L, 2L+1} and (lanes<16) {64+2L, 64+2L+1}.
// FIRST: out in z-space fp16 (*dis^2).  Else: final fp32 output (*dis).
template <bool FIRST>
__global__ void __launch_bounds__(256) hop_kernel(const unsigned int* __restrict__ zin,
                                                  void* __restrict__ outv) {
    const int node = blockIdx.x * (blockDim.x >> 5) + (threadIdx.x >> 5);
    if (node >= N_NODES) return;
    const int lane = threadIdx.x & 31;

    const unsigned int* rn = zin + (size_t)node * ROW_U;
    unsigned int u0 = rn[lane];
    unsigned int u1 = rn[32 + lane];           // live only for lanes < 16
    float2 f = __half22float2(*(__half2*)&u0);
    float a0 = f.x, a1 = f.y;
    f = __half22float2(*(__half2*)&u1);
    float a2 = f.x, a3 = f.y;

    int e = g_rowptr[node];
    const int end = g_rowptr[node + 1];

    for (; e + 3 < end; e += 4) {
        int s0 = g_col[e], s1 = g_col[e + 1], s2 = g_col[e + 2], s3 = g_col[e + 3];
        const unsigned int* r0 = zin + (size_t)s0 * ROW_U;
        const unsigned int* r1 = zin + (size_t)s1 * ROW_U;
        const unsigned int* r2 = zin + (size_t)s2 * ROW_U;
        const unsigned int* r3 = zin + (size_t)s3 * ROW_U;
        unsigned int p00 = r0[lane], p01 = r0[32 + lane];
        unsigned int p10 = r1[lane], p11 = r1[32 + lane];
        unsigned int p20 = r2[lane], p21 = r2[32 + lane];
        unsigned int p30 = r3[lane], p31 = r3[32 + lane];
        float2 t;
        t = __half22float2(*(__half2*)&p00); a0 += t.x; a1 += t.y;
        t = __half22float2(*(__half2*)&p01); a2 += t.x; a3 += t.y;
        t = __half22float2(*(__half2*)&p10); a0 += t.x; a1 += t.y;
        t = __half22float2(*(__half2*)&p11); a2 += t.x; a3 += t.y;
        t = __half22float2(*(__half2*)&p20); a0 += t.x; a1 += t.y;
        t = __half22float2(*(__half2*)&p21); a2 += t.x; a3 += t.y;
        t = __half22float2(*(__half2*)&p30); a0 += t.x; a1 += t.y;
        t = __half22float2(*(__half2*)&p31); a2 += t.x; a3 += t.y;
    }
    for (; e < end; e++) {
        int s = g_col[e];
        const unsigned int* r = zin + (size_t)s * ROW_U;
        unsigned int p0 = r[lane], p1 = r[32 + lane];
        float2 t;
        t = __half22float2(*(__half2*)&p0); a0 += t.x; a1 += t.y;
        t = __half22float2(*(__half2*)&p1); a2 += t.x; a3 += t.y;
    }

    float sc = g_dis[node];
    if (FIRST) {
        sc = sc * sc;
        unsigned int* ho = (unsigned int*)outv + (size_t)node * ROW_U;
        __half2 h01 = __floats2half2_rn(sc * a0, sc * a1);
        ho[lane] = *(unsigned int*)&h01;
        if (lane < 16) {
            __half2 h23 = __floats2half2_rn(sc * a2, sc * a3);
            ho[32 + lane] = *(unsigned int*)&h23;
        }
    } else {
        float2* ho = (float2*)outv + (size_t)node * (N_FEAT / 2);
        ho[lane] = make_float2(sc * a0, sc * a1);
        if (lane < 16) ho[32 + lane] = make_float2(sc * a2, sc * a3);
    }
}

// ---------------- launch --------------------------------------------------------
extern "C" void kernel_launch(void* const* d_in, const int* in_sizes, int n_in,
                              void* d_out, int out_size) {
    const float* x  = (const float*)d_in[0];
    const void*  ei = d_in[1];

    int* cnt = nullptr; unsigned int* z0 = nullptr; unsigned int* z1 = nullptr;
    cudaGetSymbolAddress((void**)&cnt, g_counts);
    cudaGetSymbolAddress((void**)&z0, g_z0h);
    cudaGetSymbolAddress((void**)&z1, g_z1h);

    const int TB = 256;
    cudaMemsetAsync(cnt, 0, N_NODES * sizeof(int));
    detect_kernel<<<1, 256>>>(ei);
    degree_kernel<<<(N_EDGES + TB - 1) / TB, TB>>>(ei);
    reduce_dis_kernel<<<N_CHUNK, SCAN_B>>>();
    scan_write_kernel<<<N_CHUNK, SCAN_B>>>();
    scatter_kernel<<<(N_EDGES + TB - 1) / TB, TB>>>(ei);

    const size_t TOT = (size_t)N_NODES * ROW_U;
    scale_kernel<<<(int)((TOT + TB - 1) / TB), TB>>>(x);

    const int warps_per_block = TB / 32;
    const int hop_grid = (N_NODES + warps_per_block - 1) / warps_per_block;
    hop_kernel<true ><<<hop_grid, TB>>>(z0, (void*)z1);
    hop_kernel<false><<<hop_grid, TB>>>(z1, d_out);
}